// round 1
// baseline (speedup 1.0000x reference)
#include <cuda_runtime.h>
#include <cuda_bf16.h>
#include <cstdint>

#define B_ 128
#define T_ 256
#define K_ 256
#define ROWP 264  // padded bf16 row stride: 528 bytes -> conflict-free LDS.128 across rows

// Shared layout:
//   ETt  : bf16 [K_][ROWP]  (transposed exp(transitions), row = "to" column)  135168 B
//   es   : float[K_]         exp(state - m)                                     1024 B
//   red  : float[48]         reduction scratch; red[40] = broadcast m slot
#define SMEM_ET_BYTES (K_ * ROWP * 2)
#define SMEM_BYTES (SMEM_ET_BYTES + K_ * 4 + 48 * 4)

__global__ __launch_bounds__(256, 1)
void crf_loss_kernel(const float* __restrict__ feats,      // [B,T,K]
                     const float* __restrict__ trans,      // [K,K]
                     const int*   __restrict__ tags,       // [B,T]
                     const int*   __restrict__ lens,       // [B]
                     float*       __restrict__ out)        // [B]
{
    extern __shared__ unsigned char smem[];
    uint16_t* ETt = reinterpret_cast<uint16_t*>(smem);
    float*    es  = reinterpret_cast<float*>(smem + SMEM_ET_BYTES);
    float*    red = reinterpret_cast<float*>(smem + SMEM_ET_BYTES + K_ * 4);

    const int tid = threadIdx.x;
    const int b   = blockIdx.x;

    // ---- Build ETt[to][from] = bf16(exp(trans[from][to])), to = tid ----
    // Global reads coalesced (lane -> to), STS.128 conflict-free (33*tid + c pattern).
    {
        const float* tcol = trans + tid;
        #pragma unroll 4
        for (int c = 0; c < K_ / 8; ++c) {
            float v[8];
            #pragma unroll
            for (int j = 0; j < 8; ++j)
                v[j] = __expf(tcol[(c * 8 + j) * K_]);
            uint32_t p[4];
            #pragma unroll
            for (int j = 0; j < 4; ++j) {
                __nv_bfloat162 h = __floats2bfloat162_rn(v[2 * j], v[2 * j + 1]);
                p[j] = *reinterpret_cast<uint32_t*>(&h);
            }
            *reinterpret_cast<uint4*>(&ETt[tid * ROWP + c * 8]) =
                make_uint4(p[0], p[1], p[2], p[3]);
        }
    }

    const int len = lens[b];
    const float* fb = feats + (size_t)b * T_ * K_;

    // state0 = f[0]  (mask[0] always true since len >= 1)
    float state = fb[tid];
    if (tid == 0) red[40] = state;   // cheap "m" for next step: state[0]
    __syncthreads();                 // ETt build + red[40] visible

    // ---- forward recurrence ----
    for (int t = 1; t < len; ++t) {
        float fv = fb[t * K_ + tid];       // prefetch emissions (overlaps matvec latency)
        float m  = red[40];
        es[tid]  = __expf(state - m);      // |state - m| bounded ~8 -> safe
        __syncthreads();

        float a0 = 0.f, a1 = 0.f, a2 = 0.f, a3 = 0.f;
        const uint4* eptr = reinterpret_cast<const uint4*>(&ETt[tid * ROWP]);
        #pragma unroll
        for (int c = 0; c < 32; ++c) {
            uint4  e4 = eptr[c];                                        // 8 bf16 ET values
            float4 s0 = *reinterpret_cast<const float4*>(&es[c * 8]);    // broadcast
            float4 s1 = *reinterpret_cast<const float4*>(&es[c * 8 + 4]);
            a0 = fmaf(__uint_as_float(e4.x << 16),          s0.x, a0);
            a1 = fmaf(__uint_as_float(e4.x & 0xffff0000u),  s0.y, a1);
            a2 = fmaf(__uint_as_float(e4.y << 16),          s0.z, a2);
            a3 = fmaf(__uint_as_float(e4.y & 0xffff0000u),  s0.w, a3);
            a0 = fmaf(__uint_as_float(e4.z << 16),          s1.x, a0);
            a1 = fmaf(__uint_as_float(e4.z & 0xffff0000u),  s1.y, a1);
            a2 = fmaf(__uint_as_float(e4.w << 16),          s1.z, a2);
            a3 = fmaf(__uint_as_float(e4.w & 0xffff0000u),  s1.w, a3);
        }
        float sum = (a0 + a1) + (a2 + a3);
        state = fv + m + __logf(sum);
        if (tid == 0) red[40] = state;
        __syncthreads();   // orders es read-before-next-write and red[40] write-before-read
    }

    // ---- forward_score = logsumexp(state) ----
    float v = state;
    #pragma unroll
    for (int o = 16; o > 0; o >>= 1)
        v = fmaxf(v, __shfl_xor_sync(0xffffffffu, v, o));
    if ((tid & 31) == 0) red[tid >> 5] = v;
    __syncthreads();
    float m8 = red[0];
    #pragma unroll
    for (int i = 1; i < 8; ++i) m8 = fmaxf(m8, red[i]);

    float e = __expf(state - m8);
    #pragma unroll
    for (int o = 16; o > 0; o >>= 1)
        e += __shfl_xor_sync(0xffffffffu, e, o);
    __syncthreads();                       // red[0..7] reads done before reuse of red[8..15]
    if ((tid & 31) == 0) red[8 + (tid >> 5)] = e;
    __syncthreads();
    float ssum = red[8];
    #pragma unroll
    for (int i = 1; i < 8; ++i) ssum += red[8 + i];
    float forward = m8 + __logf(ssum);

    // ---- gold path score ----  (one thread per timestep; T_ == blockDim)
    float u = 0.f;
    if (tid < len) {
        int tg = tags[b * T_ + tid];
        u = fb[tid * K_ + tg];
        if (tid + 1 < len) {
            int tg2 = tags[b * T_ + tid + 1];
            u += trans[tg * K_ + tg2];
        }
    }
    #pragma unroll
    for (int o = 16; o > 0; o >>= 1)
        u += __shfl_xor_sync(0xffffffffu, u, o);
    __syncthreads();
    if ((tid & 31) == 0) red[24 + (tid >> 5)] = u;
    __syncthreads();
    if (tid == 0) {
        float us = red[24];
        #pragma unroll
        for (int i = 1; i < 8; ++i) us += red[24 + i];
        out[b] = forward - us;
    }
}

extern "C" void kernel_launch(void* const* d_in, const int* in_sizes, int n_in,
                              void* d_out, int out_size) {
    const float* feats = (const float*)d_in[0];
    const float* trans = (const float*)d_in[1];
    const int*   tags  = (const int*)d_in[2];
    const int*   lens  = (const int*)d_in[3];
    float*       out   = (float*)d_out;

    cudaFuncSetAttribute(crf_loss_kernel,
                         cudaFuncAttributeMaxDynamicSharedMemorySize, SMEM_BYTES);
    crf_loss_kernel<<<B_, 256, SMEM_BYTES>>>(feats, trans, tags, lens, out);
}

// round 2
// speedup vs baseline: 2.2021x; 2.2021x over previous
#include <cuda_runtime.h>
#include <cuda_fp16.h>
#include <cstdint>

#define B_   128
#define T_   256
#define K_   256
#define NTH  512
#define SHIFT   14.0f                   // es scaled by 2^-14 (fp16 range guard)
#define LN2     0.6931471805599453f
#define LOG2E   1.4426950408889634f
#define NEG_INF (-1e30f)

__global__ __launch_bounds__(NTH, 1)
void crf_loss_kernel(const float* __restrict__ feats,   // [B,T,K]
                     const float* __restrict__ trans,   // [K,K]
                     const int*   __restrict__ tags,    // [B,T]
                     const int*   __restrict__ lens,    // [B]
                     float*       __restrict__ out)     // [B]
{
    __shared__ __align__(16) __half es16[K_];   // exp((state-m)) * 2^-SHIFT
    __shared__ float part[NTH];                 // per-thread partial sums
    __shared__ float redm[2];                   // double-buffered m broadcast
    __shared__ float red[16];                   // warp-reduction scratch

    const int tid = threadIdx.x;
    const int to  = tid & (K_ - 1);   // output column
    const int h   = tid >> 8;         // from-half: 0 -> from[0,128), 1 -> from[128,256)
    const int b   = blockIdx.x;

    // ---- ET in registers: ET2[c] = (exp(tr[f][to]), exp(tr[f+1][to])), f = h*128 + 2c ----
    __half2 ET2[64];
    {
        const float* tp = trans + (size_t)(h * 128) * K_ + to;  // coalesced over `to`
        #pragma unroll
        for (int c = 0; c < 64; ++c) {
            float e0 = __expf(__ldg(tp + (2 * c)     * K_));
            float e1 = __expf(__ldg(tp + (2 * c + 1) * K_));
            ET2[c] = __floats2half2_rn(e0, e1);
        }
    }

    const int len = lens[b];
    const float* fb = feats + (size_t)b * T_ * K_;

    // state0 = f[0]  (len >= 1 guaranteed)
    float state = fb[to];              // meaningful for tid < K_
    float m_cur;
    if (tid == 0) redm[0] = state;
    __syncthreads();
    m_cur = redm[0];
    if (tid < K_)
        es16[to] = __float2half_rn(exp2f((state - m_cur) * LOG2E - SHIFT));
    __syncthreads();

    // ---- forward recurrence ----
    for (int t = 1; t < len; ++t) {
        float fv = 0.f;
        if (tid < K_) fv = fb[t * K_ + to];       // prefetch, overlaps matvec

        // matvec half: sum_{f in my half} ET[f][to] * es[f]
        __half2 zz = __floats2half2_rn(0.f, 0.f);
        __half2 a0 = zz, a1 = zz, a2 = zz, a3 = zz;
        const uint4* ep = reinterpret_cast<const uint4*>(es16) + h * 16;
        #pragma unroll
        for (int i = 0; i < 16; ++i) {
            uint4 v = ep[i];                      // 8 halves, broadcast within warp
            a0 = __hfma2(ET2[4 * i + 0], *reinterpret_cast<__half2*>(&v.x), a0);
            a1 = __hfma2(ET2[4 * i + 1], *reinterpret_cast<__half2*>(&v.y), a1);
            a2 = __hfma2(ET2[4 * i + 2], *reinterpret_cast<__half2*>(&v.z), a2);
            a3 = __hfma2(ET2[4 * i + 3], *reinterpret_cast<__half2*>(&v.w), a3);
        }
        float2 f0 = __half22float2(a0), f1 = __half22float2(a1);
        float2 f2 = __half22float2(a2), f3 = __half22float2(a3);
        part[tid] = ((f0.x + f0.y) + (f1.x + f1.y)) + ((f2.x + f2.y) + (f3.x + f3.y));
        __syncthreads();                           // B1: partials ready, es reads done

        if (tid < K_) {
            float s = part[to] + part[K_ + to];
            state = fv + m_cur + (SHIFT * LN2 + __logf(s));
            float m_new = redm[(t - 1) & 1];       // state_{t-1}[0]
            es16[to] = __float2half_rn(exp2f((state - m_new) * LOG2E - SHIFT));
            if (tid == 0) redm[t & 1] = state;
            m_cur = m_new;
        }
        __syncthreads();                           // B2: es + redm visible for next step
    }

    // ---- forward_score = logsumexp_{to}(state) ----
    float x = (tid < K_) ? state : NEG_INF;
    #pragma unroll
    for (int o = 16; o > 0; o >>= 1)
        x = fmaxf(x, __shfl_xor_sync(0xffffffffu, x, o));
    if ((tid & 31) == 0) red[tid >> 5] = x;
    __syncthreads();
    float bm = red[0];
    #pragma unroll
    for (int i = 1; i < 16; ++i) bm = fmaxf(bm, red[i]);
    __syncthreads();                               // red reads done before reuse

    float e = (tid < K_) ? __expf(state - bm) : 0.f;
    #pragma unroll
    for (int o = 16; o > 0; o >>= 1)
        e += __shfl_xor_sync(0xffffffffu, e, o);
    if ((tid & 31) == 0) red[tid >> 5] = e;
    __syncthreads();
    float ssum = red[0];
    #pragma unroll
    for (int i = 1; i < 16; ++i) ssum += red[i];
    float forward = bm + __logf(ssum);
    __syncthreads();                               // red reads done before reuse

    // ---- gold path score: thread tid handles timestep tid (len <= 256) ----
    float u = 0.f;
    if (tid < len) {
        int tg = tags[b * T_ + tid];
        u = fb[tid * K_ + tg];
        if (tid + 1 < len) {
            int tg2 = tags[b * T_ + tid + 1];
            u += __ldg(trans + tg * K_ + tg2);
        }
    }
    #pragma unroll
    for (int o = 16; o > 0; o >>= 1)
        u += __shfl_xor_sync(0xffffffffu, u, o);
    if ((tid & 31) == 0) red[tid >> 5] = u;
    __syncthreads();
    if (tid == 0) {
        float us = red[0];
        #pragma unroll
        for (int i = 1; i < 16; ++i) us += red[i];
        out[b] = forward - us;
    }
}

extern "C" void kernel_launch(void* const* d_in, const int* in_sizes, int n_in,
                              void* d_out, int out_size) {
    const float* feats = (const float*)d_in[0];
    const float* trans = (const float*)d_in[1];
    const int*   tags  = (const int*)d_in[2];
    const int*   lens  = (const int*)d_in[3];
    float*       out   = (float*)d_out;

    crf_loss_kernel<<<B_, NTH>>>(feats, trans, tags, lens, out);
}